// round 16
// baseline (speedup 1.0000x reference)
#include <cuda_runtime.h>
#include <cstdint>

// Problem constants
#define SQ      4096
#define HH      16
#define DD      64
#define HALFW   128
#define TQ      32                    // query rows per block
#define SPAN    288                   // key columns logically covered per block
#define PSTR    264                   // P diagonal row stride (4-row groups)
#define HALFP   (PSTR/2)              // 132
#define NIT     (HALFP/4)             // 33 float4 iterations per half-span
#define THREADS 256

// Shared memory: P only (Q overlaid on P rows; Q is dead before P is written —
// a barrier separates the QK phase's Q reads from softmax's P writes).
#define P_OFF   0
#define Q_OFF   0
#define SMEM_FLOATS (TQ*PSTR)            // 8448
#define SMEM_BYTES  (SMEM_FLOATS * 4)    // 33792 -> 3 CTAs/SM (reg-limited)

__device__ __forceinline__ void cp16(uint32_t saddr, const void* gptr, int nbytes) {
    asm volatile("cp.async.cg.shared.global [%0], [%1], 16, %2;"
                 :: "r"(saddr), "l"(gptr), "r"(nbytes) : "memory");
}

__global__ __launch_bounds__(THREADS, 3)
void win_attn_kernel(const float* __restrict__ q,
                     const float* __restrict__ k,
                     const float* __restrict__ v,
                     float* __restrict__ out,   // [H, S, D]
                     float* __restrict__ attn)  // [H, S, S]
{
    extern __shared__ float sm[];
    const int tile = blockIdx.x;           // 0..127
    const int h    = blockIdx.y;           // 0..15
    const int t0   = tile * TQ;
    const int span_start = t0 - HALFW;     // multiple of 4 (signed)
    const int tid  = threadIdx.x;
    const int w    = tid >> 5;
    const int l    = tid & 31;
    const uint32_t smb = (uint32_t)__cvta_generic_to_shared(sm);
    const float4* kg = reinterpret_cast<const float4*>(k) + (size_t)h * SQ * 16;
    const float4* vg = reinterpret_cast<const float4*>(v) + (size_t)h * SQ * 16;

    // ---------------- Stage Q tile into smem (cp.async; K/V are NOT staged) ---------
    {
        const float4* qg = reinterpret_cast<const float4*>(q) + (size_t)(h * SQ + t0) * 16;
        #pragma unroll
        for (int i = tid; i < TQ * 16; i += THREADS)
            cp16(smb + (Q_OFF) * 4 + i * 16, qg + i, 16);
        asm volatile("cp.async.commit_group;" ::: "memory");
    }

    // ---------------- EARLY: zero region of attn (warp per 4 rows, contiguous) ------
    if (attn != nullptr) {
        float4* attn4 = reinterpret_cast<float4*>(attn);
        const float4 z4 = make_float4(0.f, 0.f, 0.f, 0.f);
        #pragma unroll
        for (int rr = 0; rr < 4; rr++) {
            int r  = w * 4 + rr;
            int gr = t0 + r;
            int s4 = (gr - HALFW) >> 2; if (s4 < 0) s4 = 0;
            int e4 = (gr + HALFW) >> 2; if (e4 > 1023) e4 = 1023;
            float4* rowp = attn4 + (size_t)(h * SQ + gr) * 1024;
            #pragma unroll 1
            for (int i = l; i < s4; i += 32) rowp[i] = z4;
            #pragma unroll 1
            for (int i = e4 + 1 + l; i < 1024; i += 32) rowp[i] = z4;
        }
    }

    asm volatile("cp.async.wait_all;" ::: "memory");
    __syncthreads();

    // ---------------- QK: warp per 4 rows; K read directly via LDG (L1/L2-hot) ------
    // Clamped row index gives garbage scores for OOB columns; they are masked in
    // softmax by the same validity predicate, so no zero-fill is needed.
    const int r0 = w * 4;
    float s[4][9];
    #pragma unroll
    for (int rr = 0; rr < 4; rr++)
        #pragma unroll
        for (int u = 0; u < 9; u++) s[rr][u] = 0.f;
    {
        int jrow[9];
        #pragma unroll
        for (int u = 0; u < 9; u++) {
            int c = r0 + l + 32 * u;
            if (c > SPAN - 1) c = SPAN - 1;
            int j = span_start + c;
            if (j < 0) j = 0;
            if (j > SQ - 1) j = SQ - 1;
            jrow[u] = j;
        }
        #pragma unroll 2
        for (int d4 = 0; d4 < 16; d4++) {
            float4 qv[4];
            #pragma unroll
            for (int rr = 0; rr < 4; rr++)
                qv[rr] = *reinterpret_cast<const float4*>(sm + Q_OFF + (r0 + rr) * DD + d4 * 4);
            #pragma unroll
            for (int u = 0; u < 9; u++) {
                float4 kv = __ldg(kg + (size_t)jrow[u] * 16 + d4);
                #pragma unroll
                for (int rr = 0; rr < 4; rr++) {
                    s[rr][u] += qv[rr].x * kv.x;
                    s[rr][u] += qv[rr].y * kv.y;
                    s[rr][u] += qv[rr].z * kv.z;
                    s[rr][u] += qv[rr].w * kv.w;
                }
            }
        }
    }
    __syncthreads();   // all Q smem reads complete; P region may now be written

    // ---------------- Softmax + write P (4-row diagonal layout, PSTR=264) -----------
    // P[r][o] = prob for span col c = (r & ~3) + o. All o in [0,264) written; masked
    // entries (incl. o in [260,264)) are exact 0 (expf(-1e30) == 0).
    #pragma unroll
    for (int rr = 0; rr < 4; rr++) {
        const int r = r0 + rr;
        float sv[9];
        float m = -3.0e38f;
        #pragma unroll
        for (int u = 0; u < 9; u++) {
            int o   = l + 32 * u;
            int off = o - rr;                 // position within row window [0,256]
            int j   = span_start + r0 + o;
            bool valid = (off >= 0) & (off <= 2 * HALFW) & (j >= 0) & (j < SQ);
            sv[u] = valid ? s[rr][u] * 0.125f : -1.0e30f;
            m = fmaxf(m, sv[u]);
        }
        #pragma unroll
        for (int o = 16; o > 0; o >>= 1)
            m = fmaxf(m, __shfl_xor_sync(0xffffffffu, m, o));
        float sum = 0.f;
        #pragma unroll
        for (int u = 0; u < 9; u++) {
            sv[u] = __expf(sv[u] - m);
            sum += sv[u];
        }
        #pragma unroll
        for (int o = 16; o > 0; o >>= 1)
            sum += __shfl_xor_sync(0xffffffffu, sum, o);
        const float inv = __fdividef(1.f, sum);
        #pragma unroll
        for (int u = 0; u < 9; u++) {
            int o = l + 32 * u;
            if (o < PSTR)
                sm[P_OFF + r * PSTR + o] = sv[u] * inv;
        }
    }
    __syncthreads();   // P visible block-wide

    // ---------------- Phase C: band stores of attn (drain under PV FMA) -------------
    // For row r: o = c0 - (r&~3) lands exactly in [0, 259] (verified index algebra).
    if (attn != nullptr) {
        float4* attn4 = reinterpret_cast<float4*>(attn);
        #pragma unroll
        for (int rr = 0; rr < 4; rr++) {
            int r  = r0 + rr;
            int gr = t0 + r;
            int s4 = (gr - HALFW) >> 2; if (s4 < 0) s4 = 0;
            int e4 = (gr + HALFW) >> 2; if (e4 > 1023) e4 = 1023;
            float4* rowp = attn4 + (size_t)(h * SQ + gr) * 1024;
            const float* pr = sm + P_OFF + r * PSTR - (r & ~3);  // index by c0 = 4i - span_start
            #pragma unroll 1
            for (int i = s4 + l; i <= e4; i += 32) {
                int c0 = 4 * i - span_start;                     // o in [0,259], 16B-aligned
                rowp[i] = *reinterpret_cast<const float4*>(pr + c0);
            }
        }
    }

    // ---------------- PV: warp per 4 rows, half-span split across lane halves; V via
    //                  direct LDG (clamped; P=0 where masked so OOB contributes 0) ---
    {
        const int half = l >> 4;          // 0: o in [0,132), 1: o in [132,264)
        const int cq   = l & 15;          // d-column group
        const int ra   = w * 4;           // rows ra..ra+3

        float4 acc[4];
        #pragma unroll
        for (int rr = 0; rr < 4; rr++) acc[rr] = make_float4(0.f, 0.f, 0.f, 0.f);

        const float4* p4[4];
        #pragma unroll
        for (int rr = 0; rr < 4; rr++)
            p4[rr] = reinterpret_cast<const float4*>(sm + P_OFF + (ra + rr) * PSTR) + half * NIT;
        const int jbase = span_start + ra + half * HALFP;   // V row = jbase + 4*i + t

        #pragma unroll 1
        for (int i = 0; i < NIT; i++) {
            float4 x0 = p4[0][i];
            float4 x1 = p4[1][i];
            float4 x2 = p4[2][i];
            float4 x3 = p4[3][i];
            #pragma unroll
            for (int t = 0; t < 4; t++) {
                int j = jbase + 4 * i + t;
                if (j < 0) j = 0;
                if (j > SQ - 1) j = SQ - 1;
                float4 vv = __ldg(vg + (size_t)j * 16 + cq);
                float f0 = (t == 0) ? x0.x : (t == 1) ? x0.y : (t == 2) ? x0.z : x0.w;
                float f1 = (t == 0) ? x1.x : (t == 1) ? x1.y : (t == 2) ? x1.z : x1.w;
                float f2 = (t == 0) ? x2.x : (t == 1) ? x2.y : (t == 2) ? x2.z : x2.w;
                float f3 = (t == 0) ? x3.x : (t == 1) ? x3.y : (t == 2) ? x3.z : x3.w;
                acc[0].x += f0 * vv.x; acc[0].y += f0 * vv.y; acc[0].z += f0 * vv.z; acc[0].w += f0 * vv.w;
                acc[1].x += f1 * vv.x; acc[1].y += f1 * vv.y; acc[1].z += f1 * vv.z; acc[1].w += f1 * vv.w;
                acc[2].x += f2 * vv.x; acc[2].y += f2 * vv.y; acc[2].z += f2 * vv.z; acc[2].w += f2 * vv.w;
                acc[3].x += f3 * vv.x; acc[3].y += f3 * vv.y; acc[3].z += f3 * vv.z; acc[3].w += f3 * vv.w;
            }
        }

        // Cross-half reduction: lane (0,cq) += lane (1,cq)
        #pragma unroll
        for (int rr = 0; rr < 4; rr++) {
            acc[rr].x += __shfl_xor_sync(0xffffffffu, acc[rr].x, 16);
            acc[rr].y += __shfl_xor_sync(0xffffffffu, acc[rr].y, 16);
            acc[rr].z += __shfl_xor_sync(0xffffffffu, acc[rr].z, 16);
            acc[rr].w += __shfl_xor_sync(0xffffffffu, acc[rr].w, 16);
        }
        if (half == 0) {
            float4* out4 = reinterpret_cast<float4*>(out);
            #pragma unroll
            for (int rr = 0; rr < 4; rr++)
                out4[(size_t)(h * SQ + t0 + ra + rr) * 16 + cq] = acc[rr];
        }
    }
}

extern "C" void kernel_launch(void* const* d_in, const int* in_sizes, int n_in,
                              void* d_out, int out_size) {
    const float* q = (const float*)d_in[0];
    const float* k = (const float*)d_in[1];
    const float* v = (const float*)d_in[2];
    float* out = (float*)d_out;

    const long long OUT_ELEMS = (long long)HH * SQ * DD;  // 4,194,304
    float* attn = ((long long)out_size > OUT_ELEMS) ? (out + OUT_ELEMS) : nullptr;

    cudaFuncSetAttribute(win_attn_kernel,
                         cudaFuncAttributeMaxDynamicSharedMemorySize, SMEM_BYTES);

    dim3 grid(SQ / TQ, HH);
    win_attn_kernel<<<grid, THREADS, SMEM_BYTES>>>(q, k, v, out, attn);
}

// round 17
// speedup vs baseline: 2.1475x; 2.1475x over previous
#include <cuda_runtime.h>
#include <cstdint>

// Problem constants
#define SQ      4096
#define HH      16
#define DD      64
#define HALFW   128
#define TQ      32                    // query rows per block
#define SPAN    288                   // key columns logically covered per block
#define SPAN_LD 292                   // KV rows resident (PV half-split reads to ra+263 <= 291)
#define KSTR    68                    // K/V smem row stride (floats): 272B -> conflict-free LDS.128
#define PSTR    264                   // P diagonal row stride (4-row groups), mult of 8
#define HALFP   (PSTR/2)              // 132
#define NIT     (HALFP/4)             // 33 float4 iterations per half-span
#define THREADS 256

// Shared memory layout (floats). P (diagonal layout) first; Q overlays P rows 0..7
// (Q is dead before any P write thanks to the barrier after the QK phase).
#define P_OFF   0
#define Q_OFF   0
#define KV_OFF  (TQ*PSTR)                    // 8448
#define SMEM_FLOATS (KV_OFF + SPAN_LD*KSTR) // 28304
#define SMEM_BYTES  (SMEM_FLOATS * 4)       // 113216 -> 2 CTAs/SM

__device__ __forceinline__ void cp16(uint32_t saddr, const void* gptr, int nbytes) {
    asm volatile("cp.async.cg.shared.global [%0], [%1], 16, %2;"
                 :: "r"(saddr), "l"(gptr), "r"(nbytes) : "memory");
}

__global__ __launch_bounds__(THREADS, 2)
void win_attn_kernel(const float* __restrict__ q,
                     const float* __restrict__ k,
                     const float* __restrict__ v,
                     float* __restrict__ out,   // [H, S, D]
                     float* __restrict__ attn)  // [H, S, S]
{
    extern __shared__ float sm[];
    const int tile = blockIdx.x;           // 0..127
    const int h    = blockIdx.y;           // 0..15
    const int t0   = tile * TQ;
    const int span_start = t0 - HALFW;     // multiple of 4 (signed)
    const int tid  = threadIdx.x;
    const int w    = tid >> 5;
    const int l    = tid & 31;
    const uint32_t smb = (uint32_t)__cvta_generic_to_shared(sm);

    // ---------------- Issue Q + K cp.async (overlap with zero stores) ----------------
    {
        const float4* qg = reinterpret_cast<const float4*>(q) + (size_t)(h * SQ + t0) * 16;
        #pragma unroll
        for (int i = tid; i < TQ * 16; i += THREADS)
            cp16(smb + (Q_OFF) * 4 + i * 16, qg + i, 16);

        const float4* kg = reinterpret_cast<const float4*>(k) + (size_t)h * SQ * 16;
        #pragma unroll 2
        for (int i = tid; i < SPAN_LD * 16; i += THREADS) {
            int c  = i >> 4;
            int d4 = i & 15;
            int j  = span_start + c;
            int jc = (j < 0) ? 0 : ((j >= SQ) ? 0 : j);
            int n  = (j >= 0 && j < SQ) ? 16 : 0;     // n=0 -> zero-fill
            cp16(smb + (KV_OFF + c * KSTR + d4 * 4) * 4, kg + (size_t)jc * 16 + d4, n);
        }
        asm volatile("cp.async.commit_group;" ::: "memory");
    }

    // ---------------- EARLY: zero region of attn (warp per 4 rows, contiguous) ------
    if (attn != nullptr) {
        float4* attn4 = reinterpret_cast<float4*>(attn);
        const float4 z4 = make_float4(0.f, 0.f, 0.f, 0.f);
        #pragma unroll
        for (int rr = 0; rr < 4; rr++) {
            int r  = w * 4 + rr;
            int gr = t0 + r;
            int s4 = (gr - HALFW) >> 2; if (s4 < 0) s4 = 0;
            int e4 = (gr + HALFW) >> 2; if (e4 > 1023) e4 = 1023;
            float4* rowp = attn4 + (size_t)(h * SQ + gr) * 1024;
            #pragma unroll 1
            for (int i = l; i < s4; i += 32) rowp[i] = z4;
            #pragma unroll 1
            for (int i = e4 + 1 + l; i < 1024; i += 32) rowp[i] = z4;
        }
    }

    asm volatile("cp.async.wait_all;" ::: "memory");
    __syncthreads();

    // ---------------- Phase A1: banded QK scores into registers (warp per 4 rows) ---
    const int r0 = w * 4;
    float s[4][9];
    #pragma unroll
    for (int rr = 0; rr < 4; rr++)
        #pragma unroll
        for (int u = 0; u < 9; u++) s[rr][u] = 0.f;
    {
        int cidx[9];
        #pragma unroll
        for (int u = 0; u < 9; u++) {
            int c = r0 + l + 32 * u;
            cidx[u] = (c < SPAN) ? c : (SPAN - 1);
        }
        #pragma unroll 2
        for (int d4 = 0; d4 < 16; d4++) {
            float4 qv[4];
            #pragma unroll
            for (int rr = 0; rr < 4; rr++)
                qv[rr] = *reinterpret_cast<const float4*>(sm + Q_OFF + (r0 + rr) * DD + d4 * 4);
            #pragma unroll
            for (int u = 0; u < 9; u++) {
                float4 kv = *reinterpret_cast<const float4*>(sm + KV_OFF + cidx[u] * KSTR + d4 * 4);
                #pragma unroll
                for (int rr = 0; rr < 4; rr++) {
                    s[rr][u] += qv[rr].x * kv.x;
                    s[rr][u] += qv[rr].y * kv.y;
                    s[rr][u] += qv[rr].z * kv.z;
                    s[rr][u] += qv[rr].w * kv.w;
                }
            }
        }
    }
    __syncthreads();   // all Q/K smem reads complete

    // ---------------- Issue V cp.async (overwrites K region; hides under softmax) ---
    {
        const float4* vg = reinterpret_cast<const float4*>(v) + (size_t)h * SQ * 16;
        #pragma unroll 2
        for (int i = tid; i < SPAN_LD * 16; i += THREADS) {
            int c  = i >> 4;
            int d4 = i & 15;
            int j  = span_start + c;
            int jc = (j < 0) ? 0 : ((j >= SQ) ? 0 : j);
            int n  = (j >= 0 && j < SQ) ? 16 : 0;
            cp16(smb + (KV_OFF + c * KSTR + d4 * 4) * 4, vg + (size_t)jc * 16 + d4, n);
        }
        asm volatile("cp.async.commit_group;" ::: "memory");
    }

    // ---------------- Phase A2: softmax + write P (4-row diagonal layout, PSTR=264) --
    // P[r][o] = prob for span col c = (r & ~3) + o. All o in [0,264) written; masked
    // entries (incl. o in [260,264)) are exact 0 (expf(-1e30) == 0).
    #pragma unroll
    for (int rr = 0; rr < 4; rr++) {
        const int r = r0 + rr;
        float sv[9];
        float m = -3.0e38f;
        #pragma unroll
        for (int u = 0; u < 9; u++) {
            int o   = l + 32 * u;
            int off = o - rr;                 // position within row window [0,256]
            int j   = span_start + r0 + o;
            bool valid = (off >= 0) & (off <= 2 * HALFW) & (j >= 0) & (j < SQ);
            sv[u] = valid ? s[rr][u] * 0.125f : -1.0e30f;
            m = fmaxf(m, sv[u]);
        }
        #pragma unroll
        for (int o = 16; o > 0; o >>= 1)
            m = fmaxf(m, __shfl_xor_sync(0xffffffffu, m, o));
        float sum = 0.f;
        #pragma unroll
        for (int u = 0; u < 9; u++) {
            sv[u] = __expf(sv[u] - m);
            sum += sv[u];
        }
        #pragma unroll
        for (int o = 16; o > 0; o >>= 1)
            sum += __shfl_xor_sync(0xffffffffu, sum, o);
        const float inv = __fdividef(1.f, sum);
        #pragma unroll
        for (int u = 0; u < 9; u++) {
            int o = l + 32 * u;
            if (o < PSTR)
                sm[P_OFF + r * PSTR + o] = sv[u] * inv;
        }
    }

    asm volatile("cp.async.wait_all;" ::: "memory");
    __syncthreads();   // P complete block-wide, V landed

    // ---------------- Phase C: band stores of attn (drain under Phase B FMA) --------
    // For row r: o = c0 - (r&~3) lands exactly in [0, 259] (verified index algebra).
    if (attn != nullptr) {
        float4* attn4 = reinterpret_cast<float4*>(attn);
        #pragma unroll
        for (int rr = 0; rr < 4; rr++) {
            int r  = r0 + rr;
            int gr = t0 + r;
            int s4 = (gr - HALFW) >> 2; if (s4 < 0) s4 = 0;
            int e4 = (gr + HALFW) >> 2; if (e4 > 1023) e4 = 1023;
            float4* rowp = attn4 + (size_t)(h * SQ + gr) * 1024;
            const float* pr = sm + P_OFF + r * PSTR - (r & ~3);  // index by c0 = 4i - span_start
            #pragma unroll 1
            for (int i = s4 + l; i <= e4; i += 32) {
                int c0 = 4 * i - span_start;                     // o in [0,259], 16B-aligned
                rowp[i] = *reinterpret_cast<const float4*>(pr + c0);
            }
        }
    }

    // ---------------- Phase B: out = P * V; warp per 4 rows, half-span split across
    //                  lane halves, shfl-xor(16) reduction (all 8 warps busy) --------
    {
        const int half = l >> 4;          // 0: o in [0,132), 1: o in [132,264)
        const int cq   = l & 15;          // d-column group
        const int ra   = w * 4;           // rows ra..ra+3; group base = ra (ra % 4 == 0)

        float4 acc[4];
        #pragma unroll
        for (int rr = 0; rr < 4; rr++) acc[rr] = make_float4(0.f, 0.f, 0.f, 0.f);

        const float4* p4[4];
        #pragma unroll
        for (int rr = 0; rr < 4; rr++)
            p4[rr] = reinterpret_cast<const float4*>(sm + P_OFF + (ra + rr) * PSTR) + half * NIT;
        const float* vb = sm + KV_OFF + (ra + half * HALFP) * KSTR + cq * 4;  // V row = ra + o

        #pragma unroll 1
        for (int i = 0; i < NIT; i++) {
            float4 x0 = p4[0][i];
            float4 x1 = p4[1][i];
            float4 x2 = p4[2][i];
            float4 x3 = p4[3][i];
            const float* vo = vb + (4 * i) * KSTR;
            float4 vv;
            vv = *reinterpret_cast<const float4*>(vo);
            acc[0].x += x0.x*vv.x; acc[0].y += x0.x*vv.y; acc[0].z += x0.x*vv.z; acc[0].w += x0.x*vv.w;
            acc[1].x += x1.x*vv.x; acc[1].y += x1.x*vv.y; acc[1].z += x1.x*vv.z; acc[1].w += x1.x*vv.w;
            acc[2].x += x2.x*vv.x; acc[2].y += x2.x*vv.y; acc[2].z += x2.x*vv.z; acc[2].w += x2.x*vv.w;
            acc[3].x += x3.x*vv.x; acc[3].y += x3.x*vv.y; acc[3].z += x3.x*vv.z; acc[3].w += x3.x*vv.w;
            vv = *reinterpret_cast<const float4*>(vo + KSTR);
            acc[0].x += x0.y*vv.x; acc[0].y += x0.y*vv.y; acc[0].z += x0.y*vv.z; acc[0].w += x0.y*vv.w;
            acc[1].x += x1.y*vv.x; acc[1].y += x1.y*vv.y; acc[1].z += x1.y*vv.z; acc[1].w += x1.y*vv.w;
            acc[2].x += x2.y*vv.x; acc[2].y += x2.y*vv.y; acc[2].z += x2.y*vv.z; acc[2].w += x2.y*vv.w;
            acc[3].x += x3.y*vv.x; acc[3].y += x3.y*vv.y; acc[3].z += x3.y*vv.z; acc[3].w += x3.y*vv.w;
            vv = *reinterpret_cast<const float4*>(vo + 2 * KSTR);
            acc[0].x += x0.z*vv.x; acc[0].y += x0.z*vv.y; acc[0].z += x0.z*vv.z; acc[0].w += x0.z*vv.w;
            acc[1].x += x1.z*vv.x; acc[1].y += x1.z*vv.y; acc[1].z += x1.z*vv.z; acc[1].w += x1.z*vv.w;
            acc[2].x += x2.z*vv.x; acc[2].y += x2.z*vv.y; acc[2].z += x2.z*vv.z; acc[2].w += x2.z*vv.w;
            acc[3].x += x3.z*vv.x; acc[3].y += x3.z*vv.y; acc[3].z += x3.z*vv.z; acc[3].w += x3.z*vv.w;
            vv = *reinterpret_cast<const float4*>(vo + 3 * KSTR);
            acc[0].x += x0.w*vv.x; acc[0].y += x0.w*vv.y; acc[0].z += x0.w*vv.z; acc[0].w += x0.w*vv.w;
            acc[1].x += x1.w*vv.x; acc[1].y += x1.w*vv.y; acc[1].z += x1.w*vv.z; acc[1].w += x1.w*vv.w;
            acc[2].x += x2.w*vv.x; acc[2].y += x2.w*vv.y; acc[2].z += x2.w*vv.z; acc[2].w += x2.w*vv.w;
            acc[3].x += x3.w*vv.x; acc[3].y += x3.w*vv.y; acc[3].z += x3.w*vv.z; acc[3].w += x3.w*vv.w;
        }

        // Cross-half reduction: lane (0,cq) += lane (1,cq)
        #pragma unroll
        for (int rr = 0; rr < 4; rr++) {
            acc[rr].x += __shfl_xor_sync(0xffffffffu, acc[rr].x, 16);
            acc[rr].y += __shfl_xor_sync(0xffffffffu, acc[rr].y, 16);
            acc[rr].z += __shfl_xor_sync(0xffffffffu, acc[rr].z, 16);
            acc[rr].w += __shfl_xor_sync(0xffffffffu, acc[rr].w, 16);
        }
        if (half == 0) {
            float4* out4 = reinterpret_cast<float4*>(out);
            #pragma unroll
            for (int rr = 0; rr < 4; rr++)
                out4[(size_t)(h * SQ + t0 + ra + rr) * 16 + cq] = acc[rr];
        }
    }
}

extern "C" void kernel_launch(void* const* d_in, const int* in_sizes, int n_in,
                              void* d_out, int out_size) {
    const float* q = (const float*)d_in[0];
    const float* k = (const float*)d_in[1];
    const float* v = (const float*)d_in[2];
    float* out = (float*)d_out;

    const long long OUT_ELEMS = (long long)HH * SQ * DD;  // 4,194,304
    float* attn = ((long long)out_size > OUT_ELEMS) ? (out + OUT_ELEMS) : nullptr;

    cudaFuncSetAttribute(win_attn_kernel,
                         cudaFuncAttributeMaxDynamicSharedMemorySize, SMEM_BYTES);

    dim3 grid(SQ / TQ, HH);
    win_attn_kernel<<<grid, THREADS, SMEM_BYTES>>>(q, k, v, out, attn);
}